// round 7
// baseline (speedup 1.0000x reference)
#include <cuda_runtime.h>
#include <cuda_bf16.h>
#include <cstdint>

// out[b,k] = sum_{i,j} x[b,i] W[k,i,j] x[b,j]
// Diagonal pair enumeration: k-step kk (0..8), slot c (0..15) -> pair (i=c, j=(c+kk)&15).
// GEMM per warp-tile: D[16 x 16] += A[16 x 144] * B[144 x 16] via mma.sync.m16n8k16 bf16
// with hi/lo split: D = Ahi*Bhi + Alo*Bhi + Ahi*Blo.
// R7: B fragments live in REGISTERS (loaded once, warp-uniform); sX padded to
// stride 20 to cut bank conflicts; hi/lo accumulators separated (4 HMMA chains).

#define NKST 9
#define ITER 4
#define WARPS 4
#define ROWS_PER_BLOCK (WARPS * ITER * 16)  // 256

// B fragment tables: [kk][nt][lane] -> uint2 {b0pack, b1pack}
__device__ uint2 g_BH[NKST * 2 * 32];
__device__ uint2 g_BL[NKST * 2 * 32];

__device__ __forceinline__ float wd_val(const float* W, int d, int i, int n) {
    int j = (i + d) & 15;
    float v = W[n * 256 + i * 16 + j];
    if (d == 0) return v;
    if (d == 8 && i >= 8) return 0.0f;
    return v + W[n * 256 + j * 16 + i];
}

__device__ __forceinline__ uint32_t pack_bf16_pair(float lo_elem, float hi_elem) {
    __nv_bfloat16 l = __float2bfloat16(lo_elem);
    __nv_bfloat16 h = __float2bfloat16(hi_elem);
    return (uint32_t)*(uint16_t*)&l | ((uint32_t)*(uint16_t*)&h << 16);
}

__global__ void prep_kernel(const float* __restrict__ W) {
    int id = blockIdx.x * blockDim.x + threadIdx.x;
    if (id >= NKST * 2 * 32) return;
    int lane = id & 31;
    int nt = (id >> 5) & 1;
    int kk = id >> 6;
    int gr = lane >> 2, tc = lane & 3;
    int n = nt * 8 + gr;

    float w[4];
    w[0] = wd_val(W, kk, tc * 2, n);
    w[1] = wd_val(W, kk, tc * 2 + 1, n);
    w[2] = wd_val(W, kk, tc * 2 + 8, n);
    w[3] = wd_val(W, kk, tc * 2 + 9, n);

    float hi[4], lo[4];
#pragma unroll
    for (int e = 0; e < 4; ++e) {
        __nv_bfloat16 h = __float2bfloat16(w[e]);
        hi[e] = __bfloat162float(h);
        lo[e] = w[e] - hi[e];
    }
    g_BH[id] = make_uint2(pack_bf16_pair(hi[0], hi[1]), pack_bf16_pair(hi[2], hi[3]));
    g_BL[id] = make_uint2(pack_bf16_pair(lo[0], lo[1]), pack_bf16_pair(lo[2], lo[3]));
}

__device__ __forceinline__ uint32_t prmt_hi(float a, float b) {
    uint32_t r;
    asm("prmt.b32 %0, %1, %2, 0x7632;"
        : "=r"(r) : "r"(__float_as_uint(a)), "r"(__float_as_uint(b)));
    return r;
}
__device__ __forceinline__ float hipart(float a) {
    return __uint_as_float(__float_as_uint(a) & 0xFFFF0000u);
}

__device__ __forceinline__ void hmma(float& d0, float& d1, float& d2, float& d3,
                                     uint32_t a0, uint32_t a1, uint32_t a2, uint32_t a3,
                                     uint32_t b0, uint32_t b1) {
    asm volatile(
        "mma.sync.aligned.m16n8k16.row.col.f32.bf16.bf16.f32 "
        "{%0,%1,%2,%3}, {%4,%5,%6,%7}, {%8,%9}, {%0,%1,%2,%3};"
        : "+f"(d0), "+f"(d1), "+f"(d2), "+f"(d3)
        : "r"(a0), "r"(a1), "r"(a2), "r"(a3), "r"(b0), "r"(b1));
}

__global__ void __launch_bounds__(128, 3)
bilinear_hmma(const float* __restrict__ x, float* __restrict__ out) {
    __shared__ float sX[WARPS][16][20];   // padded stride: fewer LDS bank conflicts

    int tid = threadIdx.x;
    int wid = tid >> 5, lane = tid & 31;
    int gr = lane >> 2, tc = lane & 3;
    int i0 = tc * 2;

    // B fragments -> registers (iteration-invariant, broadcast loads)
    uint2 BH[NKST][2], BL[NKST][2];
#pragma unroll
    for (int kk = 0; kk < NKST; ++kk) {
#pragma unroll
        for (int nt = 0; nt < 2; ++nt) {
            BH[kk][nt] = g_BH[(kk * 2 + nt) * 32 + lane];
            BL[kk][nt] = g_BL[(kk * 2 + nt) * 32 + lane];
        }
    }

#pragma unroll 1
    for (int it = 0; it < ITER; ++it) {
        int tb = blockIdx.x * ROWS_PER_BLOCK + (wid * ITER + it) * 16;

        // stage this warp's 16 x-rows into smem (coalesced)
        {
            const float4* g = (const float4*)(x + (size_t)tb * 16);
            float4 v0 = g[lane];
            float4 v1 = g[lane + 32];
            *(float4*)&sX[wid][lane >> 2][(lane & 3) * 4] = v0;
            *(float4*)&sX[wid][(lane + 32) >> 2][(lane & 3) * 4] = v1;
        }
        __syncwarp();

        // rotated register copies: xr[m] = x_row[(i0+m)&15] -> compile-time indices below
        float xr0[16], xr1[16];
#pragma unroll
        for (int m = 0; m < 16; m += 2) {
            int c = (i0 + m) & 15;
            float2 v0 = *(const float2*)&sX[wid][gr][c];
            float2 v1 = *(const float2*)&sX[wid][gr + 8][c];
            xr0[m] = v0.x; xr0[m + 1] = v0.y;
            xr1[m] = v1.x; xr1[m + 1] = v1.y;
        }

        // separate hi/lo accumulators: 4 independent HMMA chains
        float aH0[4] = {0.f, 0.f, 0.f, 0.f};
        float aL0[4] = {0.f, 0.f, 0.f, 0.f};
        float aH1[4] = {0.f, 0.f, 0.f, 0.f};
        float aL1[4] = {0.f, 0.f, 0.f, 0.f};

#pragma unroll
        for (int kk = 0; kk < NKST; ++kk) {
            float p0 = xr0[0] * xr0[(0 + kk) & 15];
            float p1 = xr0[1] * xr0[(1 + kk) & 15];
            float p2 = xr0[8] * xr0[(8 + kk) & 15];
            float p3 = xr0[9] * xr0[(9 + kk) & 15];
            float q0 = xr1[0] * xr1[(0 + kk) & 15];
            float q1 = xr1[1] * xr1[(1 + kk) & 15];
            float q2 = xr1[8] * xr1[(8 + kk) & 15];
            float q3 = xr1[9] * xr1[(9 + kk) & 15];

            uint32_t a0h = prmt_hi(p0, p1);
            uint32_t a1h = prmt_hi(q0, q1);
            uint32_t a2h = prmt_hi(p2, p3);
            uint32_t a3h = prmt_hi(q2, q3);

            float p0l = p0 - hipart(p0), p1l = p1 - hipart(p1);
            float p2l = p2 - hipart(p2), p3l = p3 - hipart(p3);
            float q0l = q0 - hipart(q0), q1l = q1 - hipart(q1);
            float q2l = q2 - hipart(q2), q3l = q3 - hipart(q3);

            uint32_t a0l = prmt_hi(p0l, p1l);
            uint32_t a1l = prmt_hi(q0l, q1l);
            uint32_t a2l = prmt_hi(p2l, p3l);
            uint32_t a3l = prmt_hi(q2l, q3l);

            hmma(aH0[0], aH0[1], aH0[2], aH0[3], a0h, a1h, a2h, a3h, BH[kk][0].x, BH[kk][0].y);
            hmma(aL0[0], aL0[1], aL0[2], aL0[3], a0l, a1l, a2l, a3l, BH[kk][0].x, BH[kk][0].y);
            hmma(aL0[0], aL0[1], aL0[2], aL0[3], a0h, a1h, a2h, a3h, BL[kk][0].x, BL[kk][0].y);

            hmma(aH1[0], aH1[1], aH1[2], aH1[3], a0h, a1h, a2h, a3h, BH[kk][1].x, BH[kk][1].y);
            hmma(aL1[0], aL1[1], aL1[2], aL1[3], a0l, a1l, a2l, a3l, BH[kk][1].x, BH[kk][1].y);
            hmma(aL1[0], aL1[1], aL1[2], aL1[3], a0h, a1h, a2h, a3h, BL[kk][1].x, BL[kk][1].y);
        }

        // epilogue: D m16n8 layout; combine hi+lo chains at fp32
        {
            float* o0 = out + (size_t)(tb + gr) * 16;
            float* o1 = out + (size_t)(tb + gr + 8) * 16;
            *(float2*)(o0 + tc * 2)     = make_float2(aH0[0] + aL0[0], aH0[1] + aL0[1]);
            *(float2*)(o1 + tc * 2)     = make_float2(aH0[2] + aL0[2], aH0[3] + aL0[3]);
            *(float2*)(o0 + 8 + tc * 2) = make_float2(aH1[0] + aL1[0], aH1[1] + aL1[1]);
            *(float2*)(o1 + 8 + tc * 2) = make_float2(aH1[2] + aL1[2], aH1[3] + aL1[3]);
        }
        __syncwarp();  // protect sX before next iteration overwrites it
    }
}

extern "C" void kernel_launch(void* const* d_in, const int* in_sizes, int n_in,
                              void* d_out, int out_size) {
    const float* x = (const float*)d_in[0];
    const float* W = (const float*)d_in[1];
    if (n_in >= 2 && in_sizes[0] == 4096) {  // defensive input identification
        W = (const float*)d_in[0];
        x = (const float*)d_in[1];
    }
    float* out = (float*)d_out;

    prep_kernel<<<3, 256>>>(W);  // 576 table entries

    const unsigned int B = 1048576u;
    bilinear_hmma<<<B / ROWS_PER_BLOCK, 128>>>(x, out);
}

// round 8
// speedup vs baseline: 1.0109x; 1.0109x over previous
#include <cuda_runtime.h>
#include <cuda_bf16.h>
#include <cstdint>

// out[b,k] = sum_{i,j} x[b,i] W[k,i,j] x[b,j]
// Diagonal pair enumeration: k-step kk (0..8), slot c (0..15) -> pair (i=c, j=(c+kk)&15).
// GEMM per warp-tile: D[16 x 16] += A[16 x 144] * B[144 x 16] via mma.sync.m16n8k16 bf16
// with hi/lo split: D = Ahi*Bhi + Alo*Bhi + Ahi*Blo.
// R8: BH in registers (hot, 4/6 HMMAs), BL in shared as uint4 (1 LDS.128 per kk);
// launch_bounds(128,4) to restore occupancy (the R7 lesson: issue-bound, need warps).

#define NKST 9
#define ITER 4
#define WARPS 4
#define ROWS_PER_BLOCK (WARPS * ITER * 16)  // 256

// B fragment tables: [kk][nt][lane] -> uint2 {b0pack, b1pack}
__device__ uint2 g_BH[NKST * 2 * 32];
__device__ uint2 g_BL[NKST * 2 * 32];

__device__ __forceinline__ float wd_val(const float* W, int d, int i, int n) {
    int j = (i + d) & 15;
    float v = W[n * 256 + i * 16 + j];
    if (d == 0) return v;
    if (d == 8 && i >= 8) return 0.0f;
    return v + W[n * 256 + j * 16 + i];
}

__device__ __forceinline__ uint32_t pack_bf16_pair(float lo_elem, float hi_elem) {
    __nv_bfloat16 l = __float2bfloat16(lo_elem);
    __nv_bfloat16 h = __float2bfloat16(hi_elem);
    return (uint32_t)*(uint16_t*)&l | ((uint32_t)*(uint16_t*)&h << 16);
}

__global__ void prep_kernel(const float* __restrict__ W) {
    int id = blockIdx.x * blockDim.x + threadIdx.x;
    if (id >= NKST * 2 * 32) return;
    int lane = id & 31;
    int nt = (id >> 5) & 1;
    int kk = id >> 6;
    int gr = lane >> 2, tc = lane & 3;
    int n = nt * 8 + gr;

    float w[4];
    w[0] = wd_val(W, kk, tc * 2, n);
    w[1] = wd_val(W, kk, tc * 2 + 1, n);
    w[2] = wd_val(W, kk, tc * 2 + 8, n);
    w[3] = wd_val(W, kk, tc * 2 + 9, n);

    float hi[4], lo[4];
#pragma unroll
    for (int e = 0; e < 4; ++e) {
        __nv_bfloat16 h = __float2bfloat16(w[e]);
        hi[e] = __bfloat162float(h);
        lo[e] = w[e] - hi[e];
    }
    g_BH[id] = make_uint2(pack_bf16_pair(hi[0], hi[1]), pack_bf16_pair(hi[2], hi[3]));
    g_BL[id] = make_uint2(pack_bf16_pair(lo[0], lo[1]), pack_bf16_pair(lo[2], lo[3]));
}

__device__ __forceinline__ uint32_t prmt_hi(float a, float b) {
    uint32_t r;
    asm("prmt.b32 %0, %1, %2, 0x7632;"
        : "=r"(r) : "r"(__float_as_uint(a)), "r"(__float_as_uint(b)));
    return r;
}
__device__ __forceinline__ float hipart(float a) {
    return __uint_as_float(__float_as_uint(a) & 0xFFFF0000u);
}

__device__ __forceinline__ void hmma(float& d0, float& d1, float& d2, float& d3,
                                     uint32_t a0, uint32_t a1, uint32_t a2, uint32_t a3,
                                     uint32_t b0, uint32_t b1) {
    asm volatile(
        "mma.sync.aligned.m16n8k16.row.col.f32.bf16.bf16.f32 "
        "{%0,%1,%2,%3}, {%4,%5,%6,%7}, {%8,%9}, {%0,%1,%2,%3};"
        : "+f"(d0), "+f"(d1), "+f"(d2), "+f"(d3)
        : "r"(a0), "r"(a1), "r"(a2), "r"(a3), "r"(b0), "r"(b1));
}

__global__ void __launch_bounds__(128, 4)
bilinear_hmma(const float* __restrict__ x, float* __restrict__ out) {
    __shared__ float sX[WARPS][16][20];        // padded stride vs bank conflicts
    __shared__ uint4 sBL[NKST * 32];           // {BL0.x, BL0.y, BL1.x, BL1.y} per (kk, lane)

    int tid = threadIdx.x;
    int wid = tid >> 5, lane = tid & 31;
    int gr = lane >> 2, tc = lane & 3;
    int i0 = tc * 2;

    // repack BL into smem as uint4 per (kk, lane)
    for (int i = tid; i < NKST * 32; i += 128) {
        int kk = i >> 5, ln = i & 31;
        uint2 b0 = g_BL[(kk * 2 + 0) * 32 + ln];
        uint2 b1 = g_BL[(kk * 2 + 1) * 32 + ln];
        sBL[i] = make_uint4(b0.x, b0.y, b1.x, b1.y);
    }

    // BH fragments -> registers (iteration-invariant)
    uint2 BH[NKST][2];
#pragma unroll
    for (int kk = 0; kk < NKST; ++kk) {
#pragma unroll
        for (int nt = 0; nt < 2; ++nt)
            BH[kk][nt] = g_BH[(kk * 2 + nt) * 32 + lane];
    }
    __syncthreads();

#pragma unroll 1
    for (int it = 0; it < ITER; ++it) {
        int tb = blockIdx.x * ROWS_PER_BLOCK + (wid * ITER + it) * 16;

        // stage this warp's 16 x-rows into smem (coalesced)
        {
            const float4* g = (const float4*)(x + (size_t)tb * 16);
            float4 v0 = g[lane];
            float4 v1 = g[lane + 32];
            *(float4*)&sX[wid][lane >> 2][(lane & 3) * 4] = v0;
            *(float4*)&sX[wid][(lane + 32) >> 2][(lane & 3) * 4] = v1;
        }
        __syncwarp();

        // rotated register copies: xr[m] = x_row[(i0+m)&15] -> compile-time indices below
        float xr0[16], xr1[16];
#pragma unroll
        for (int m = 0; m < 16; m += 2) {
            int c = (i0 + m) & 15;
            float2 v0 = *(const float2*)&sX[wid][gr][c];
            float2 v1 = *(const float2*)&sX[wid][gr + 8][c];
            xr0[m] = v0.x; xr0[m + 1] = v0.y;
            xr1[m] = v1.x; xr1[m + 1] = v1.y;
        }

        // separate hi/lo accumulators: 4 independent HMMA chains
        float aH0[4] = {0.f, 0.f, 0.f, 0.f};
        float aL0[4] = {0.f, 0.f, 0.f, 0.f};
        float aH1[4] = {0.f, 0.f, 0.f, 0.f};
        float aL1[4] = {0.f, 0.f, 0.f, 0.f};

#pragma unroll
        for (int kk = 0; kk < NKST; ++kk) {
            float p0 = xr0[0] * xr0[(0 + kk) & 15];
            float p1 = xr0[1] * xr0[(1 + kk) & 15];
            float p2 = xr0[8] * xr0[(8 + kk) & 15];
            float p3 = xr0[9] * xr0[(9 + kk) & 15];
            float q0 = xr1[0] * xr1[(0 + kk) & 15];
            float q1 = xr1[1] * xr1[(1 + kk) & 15];
            float q2 = xr1[8] * xr1[(8 + kk) & 15];
            float q3 = xr1[9] * xr1[(9 + kk) & 15];

            uint32_t a0h = prmt_hi(p0, p1);
            uint32_t a1h = prmt_hi(q0, q1);
            uint32_t a2h = prmt_hi(p2, p3);
            uint32_t a3h = prmt_hi(q2, q3);

            float p0l = p0 - hipart(p0), p1l = p1 - hipart(p1);
            float p2l = p2 - hipart(p2), p3l = p3 - hipart(p3);
            float q0l = q0 - hipart(q0), q1l = q1 - hipart(q1);
            float q2l = q2 - hipart(q2), q3l = q3 - hipart(q3);

            uint32_t a0l = prmt_hi(p0l, p1l);
            uint32_t a1l = prmt_hi(q0l, q1l);
            uint32_t a2l = prmt_hi(p2l, p3l);
            uint32_t a3l = prmt_hi(q2l, q3l);

            uint4 bl = sBL[kk * 32 + lane];

            hmma(aH0[0], aH0[1], aH0[2], aH0[3], a0h, a1h, a2h, a3h, BH[kk][0].x, BH[kk][0].y);
            hmma(aL0[0], aL0[1], aL0[2], aL0[3], a0l, a1l, a2l, a3l, BH[kk][0].x, BH[kk][0].y);
            hmma(aL0[0], aL0[1], aL0[2], aL0[3], a0h, a1h, a2h, a3h, bl.x, bl.y);

            hmma(aH1[0], aH1[1], aH1[2], aH1[3], a0h, a1h, a2h, a3h, BH[kk][1].x, BH[kk][1].y);
            hmma(aL1[0], aL1[1], aL1[2], aL1[3], a0l, a1l, a2l, a3l, BH[kk][1].x, BH[kk][1].y);
            hmma(aL1[0], aL1[1], aL1[2], aL1[3], a0h, a1h, a2h, a3h, bl.z, bl.w);
        }

        // epilogue: D m16n8 layout; combine hi+lo chains at fp32
        {
            float* o0 = out + (size_t)(tb + gr) * 16;
            float* o1 = out + (size_t)(tb + gr + 8) * 16;
            *(float2*)(o0 + tc * 2)     = make_float2(aH0[0] + aL0[0], aH0[1] + aL0[1]);
            *(float2*)(o1 + tc * 2)     = make_float2(aH0[2] + aL0[2], aH0[3] + aL0[3]);
            *(float2*)(o0 + 8 + tc * 2) = make_float2(aH1[0] + aL1[0], aH1[1] + aL1[1]);
            *(float2*)(o1 + 8 + tc * 2) = make_float2(aH1[2] + aL1[2], aH1[3] + aL1[3]);
        }
        __syncwarp();  // protect sX before next iteration overwrites it
    }
}

extern "C" void kernel_launch(void* const* d_in, const int* in_sizes, int n_in,
                              void* d_out, int out_size) {
    const float* x = (const float*)d_in[0];
    const float* W = (const float*)d_in[1];
    if (n_in >= 2 && in_sizes[0] == 4096) {  // defensive input identification
        W = (const float*)d_in[0];
        x = (const float*)d_in[1];
    }
    float* out = (float*)d_out;

    prep_kernel<<<3, 256>>>(W);  // 576 table entries

    const unsigned int B = 1048576u;
    bilinear_hmma<<<B / ROWS_PER_BLOCK, 128>>>(x, out);
}

// round 9
// speedup vs baseline: 1.2463x; 1.2328x over previous
#include <cuda_runtime.h>
#include <cuda_fp16.h>
#include <cstdint>

// out[b,k] = sum_{i,j} x[b,i] W[k,i,j] x[b,j]
// Diagonal pair enumeration: k-step kk (0..8), slot c (0..15) -> pair (i=c, j=(c+kk)&15).
// GEMM per warp-tile: D[16 x 16] += A[16 x 144] * B[144 x 16] via mma.sync.m16n8k16 FP16
// 2-term split: A = Ahi + Alo (f16 pair, exact to 2^-23), B = rn_f16(W) single.
// D = Ahi*Bhi + Alo*Bhi -> error ~= B rounding ~ 2^-12 (well under 1e-3).
// R9: f16 halves the correction terms (54->36 HMMA/tile), B traffic halves,
// B in smem + lean regs -> 5 CTAs/SM.

#define NKST 9
#define ITER 4
#define WARPS 4
#define ROWS_PER_BLOCK (WARPS * ITER * 16)  // 256

// B fragment table (f16 hi only): [kk][nt][lane] -> uint2 {b0pack, b1pack}
__device__ uint2 g_BH[NKST * 2 * 32];

__device__ __forceinline__ float wd_val(const float* W, int d, int i, int n) {
    int j = (i + d) & 15;
    float v = W[n * 256 + i * 16 + j];
    if (d == 0) return v;
    if (d == 8 && i >= 8) return 0.0f;
    return v + W[n * 256 + j * 16 + i];
}

__device__ __forceinline__ uint32_t pack_f16_pair(float lo_elem, float hi_elem) {
    __half l = __float2half_rn(lo_elem);
    __half h = __float2half_rn(hi_elem);
    return (uint32_t)*(uint16_t*)&l | ((uint32_t)*(uint16_t*)&h << 16);
}

__global__ void prep_kernel(const float* __restrict__ W) {
    int id = blockIdx.x * blockDim.x + threadIdx.x;
    if (id >= NKST * 2 * 32) return;
    int lane = id & 31;
    int nt = (id >> 5) & 1;
    int kk = id >> 6;
    int gr = lane >> 2, tc = lane & 3;
    int n = nt * 8 + gr;

    float w0 = wd_val(W, kk, tc * 2, n);
    float w1 = wd_val(W, kk, tc * 2 + 1, n);
    float w2 = wd_val(W, kk, tc * 2 + 8, n);
    float w3 = wd_val(W, kk, tc * 2 + 9, n);
    g_BH[id] = make_uint2(pack_f16_pair(w0, w1), pack_f16_pair(w2, w3));
}

// pack two f32 -> f16x2 (low half = first arg)
__device__ __forceinline__ uint32_t f16pack(float lo_elem, float hi_elem) {
    uint32_t r;
    asm("cvt.rn.f16x2.f32 %0, %1, %2;" : "=r"(r) : "f"(hi_elem), "f"(lo_elem));
    return r;
}
// truncate f32 to f16-exact value (10 mantissa bits kept), stays in f32
__device__ __forceinline__ float h16part(float a) {
    return __uint_as_float(__float_as_uint(a) & 0xFFFFE000u);
}

__device__ __forceinline__ void hmma(float& d0, float& d1, float& d2, float& d3,
                                     uint32_t a0, uint32_t a1, uint32_t a2, uint32_t a3,
                                     uint32_t b0, uint32_t b1) {
    asm volatile(
        "mma.sync.aligned.m16n8k16.row.col.f32.f16.f16.f32 "
        "{%0,%1,%2,%3}, {%4,%5,%6,%7}, {%8,%9}, {%0,%1,%2,%3};"
        : "+f"(d0), "+f"(d1), "+f"(d2), "+f"(d3)
        : "r"(a0), "r"(a1), "r"(a2), "r"(a3), "r"(b0), "r"(b1));
}

__global__ void __launch_bounds__(128, 5)
bilinear_hmma(const float* __restrict__ x, float* __restrict__ out) {
    __shared__ float sX[WARPS][16][20];   // padded stride vs bank conflicts
    __shared__ uint4 sB[NKST * 32];       // {Bnt0.x, Bnt0.y, Bnt1.x, Bnt1.y} per (kk, lane)

    int tid = threadIdx.x;
    int wid = tid >> 5, lane = tid & 31;
    int gr = lane >> 2, tc = lane & 3;
    int i0 = tc * 2;

    for (int i = tid; i < NKST * 32; i += 128) {
        int kk = i >> 5, ln = i & 31;
        uint2 b0 = g_BH[(kk * 2 + 0) * 32 + ln];
        uint2 b1 = g_BH[(kk * 2 + 1) * 32 + ln];
        sB[i] = make_uint4(b0.x, b0.y, b1.x, b1.y);
    }
    __syncthreads();

#pragma unroll 1
    for (int it = 0; it < ITER; ++it) {
        int tb = blockIdx.x * ROWS_PER_BLOCK + (wid * ITER + it) * 16;

        // stage this warp's 16 x-rows into smem (coalesced)
        {
            const float4* g = (const float4*)(x + (size_t)tb * 16);
            float4 v0 = g[lane];
            float4 v1 = g[lane + 32];
            *(float4*)&sX[wid][lane >> 2][(lane & 3) * 4] = v0;
            *(float4*)&sX[wid][(lane + 32) >> 2][(lane & 3) * 4] = v1;
        }
        __syncwarp();

        // rotated register copies: xr[m] = x_row[(i0+m)&15] -> compile-time indices below
        float xr0[16], xr1[16];
#pragma unroll
        for (int m = 0; m < 16; m += 2) {
            int c = (i0 + m) & 15;
            float2 v0 = *(const float2*)&sX[wid][gr][c];
            float2 v1 = *(const float2*)&sX[wid][gr + 8][c];
            xr0[m] = v0.x; xr0[m + 1] = v0.y;
            xr1[m] = v1.x; xr1[m + 1] = v1.y;
        }

        // 4 independent HMMA chains: (hi, lo) x (nt0, nt1)
        float aH0[4] = {0.f, 0.f, 0.f, 0.f};
        float aL0[4] = {0.f, 0.f, 0.f, 0.f};
        float aH1[4] = {0.f, 0.f, 0.f, 0.f};
        float aL1[4] = {0.f, 0.f, 0.f, 0.f};

#pragma unroll
        for (int kk = 0; kk < NKST; ++kk) {
            float p0 = xr0[0] * xr0[(0 + kk) & 15];
            float p1 = xr0[1] * xr0[(1 + kk) & 15];
            float p2 = xr0[8] * xr0[(8 + kk) & 15];
            float p3 = xr0[9] * xr0[(9 + kk) & 15];
            float q0 = xr1[0] * xr1[(0 + kk) & 15];
            float q1 = xr1[1] * xr1[(1 + kk) & 15];
            float q2 = xr1[8] * xr1[(8 + kk) & 15];
            float q3 = xr1[9] * xr1[(9 + kk) & 15];

            // hi = f16-exact truncation (in f32), lo = exact residual
            float h0 = h16part(p0), h1 = h16part(p1), h2 = h16part(p2), h3 = h16part(p3);
            float g0 = h16part(q0), g1 = h16part(q1), g2 = h16part(q2), g3 = h16part(q3);

            uint32_t a0h = f16pack(h0, h1);
            uint32_t a1h = f16pack(g0, g1);
            uint32_t a2h = f16pack(h2, h3);
            uint32_t a3h = f16pack(g2, g3);

            uint32_t a0l = f16pack(p0 - h0, p1 - h1);
            uint32_t a1l = f16pack(q0 - g0, q1 - g1);
            uint32_t a2l = f16pack(p2 - h2, p3 - h3);
            uint32_t a3l = f16pack(q2 - g2, q3 - g3);

            uint4 b = sB[kk * 32 + lane];

            hmma(aH0[0], aH0[1], aH0[2], aH0[3], a0h, a1h, a2h, a3h, b.x, b.y);
            hmma(aL0[0], aL0[1], aL0[2], aL0[3], a0l, a1l, a2l, a3l, b.x, b.y);
            hmma(aH1[0], aH1[1], aH1[2], aH1[3], a0h, a1h, a2h, a3h, b.z, b.w);
            hmma(aL1[0], aL1[1], aL1[2], aL1[3], a0l, a1l, a2l, a3l, b.z, b.w);
        }

        // epilogue: D m16n8 layout; combine hi+lo chains at fp32
        {
            float* o0 = out + (size_t)(tb + gr) * 16;
            float* o1 = out + (size_t)(tb + gr + 8) * 16;
            *(float2*)(o0 + tc * 2)     = make_float2(aH0[0] + aL0[0], aH0[1] + aL0[1]);
            *(float2*)(o1 + tc * 2)     = make_float2(aH0[2] + aL0[2], aH0[3] + aL0[3]);
            *(float2*)(o0 + 8 + tc * 2) = make_float2(aH1[0] + aL1[0], aH1[1] + aL1[1]);
            *(float2*)(o1 + 8 + tc * 2) = make_float2(aH1[2] + aL1[2], aH1[3] + aL1[3]);
        }
        __syncwarp();  // protect sX before next iteration overwrites it
    }
}

extern "C" void kernel_launch(void* const* d_in, const int* in_sizes, int n_in,
                              void* d_out, int out_size) {
    const float* x = (const float*)d_in[0];
    const float* W = (const float*)d_in[1];
    if (n_in >= 2 && in_sizes[0] == 4096) {  // defensive input identification
        W = (const float*)d_in[0];
        x = (const float*)d_in[1];
    }
    float* out = (float*)d_out;

    prep_kernel<<<3, 256>>>(W);  // 576 table entries

    const unsigned int B = 1048576u;
    bilinear_hmma<<<B / ROWS_PER_BLOCK, 128>>>(x, out);
}